// round 10
// baseline (speedup 1.0000x reference)
#include <cuda_runtime.h>
#include <cstdint>
#include <cstddef>

// ---------------------------------------------------------------------------
// ColorHistogramMatchingLoss — FFMA2 (packed f32x2) GEMM path.
//   hist[b,c][i][j] = sum_n w_n * rbf_u(n)[i] * rbf_v(n)[j]
// R9: 4 blocks/SM (32 warps, 4x8 thread tiles, 32 acc regs), zero-MOV inner
// loop (A pair-duplicated in smem, packed LDS.128 operands), single wave
// (576 blocks), R4's barrier structure, fused finalize.
// ---------------------------------------------------------------------------

#define D_HIST 64
#define CHUNK  64
#define SPLITS 12
#define PX_PER_SPLIT 5462            // ceil(65536/12)
#define NCHUNKS 86                   // ceil(5462/64)
#define HIST_BLOCKS (2*8*3*SPLITS)   // 576  (<= 592 slots @ 4/SM: single wave)
#define EPS_F  1e-6f
#define PLANE  65536
#define HTOT   (2*8*3*D_HIST*D_HIST)

// dynamic smem layout (bytes from base)
#define OFF_A2  0u                   // 64 k-rows x 128 floats (dup pairs) = 32768
#define OFF_B   32768u               // 64 k-rows x 64 floats            = 16384
#define OFF_RAW 49152u               // 3 x 64 floats
#define OFF_U   49920u               // 64 floats (u*50)
#define OFF_V   50176u
#define OFF_W   50432u
#define DYN_SMEM 50688

__device__ float    g_hist[HTOT];
__device__ unsigned g_done;

// ---- packed f32x2 + vector shared helpers ---------------------------------
static __device__ __forceinline__ void fma2(unsigned long long &d,
                                            unsigned long long a,
                                            unsigned long long b) {
    asm("fma.rn.f32x2 %0, %1, %2, %0;" : "+l"(d) : "l"(a), "l"(b));
}
static __device__ __forceinline__ void lds_pair(unsigned long long &a,
                                                unsigned long long &b,
                                                unsigned addr) {
    asm volatile("ld.shared.v2.u64 {%0, %1}, [%2];"
                 : "=l"(a), "=l"(b) : "r"(addr));
}
static __device__ __forceinline__ void sts_dup(unsigned addr, float v) {
    asm volatile("st.shared.v2.f32 [%0], {%1, %1};" :: "r"(addr), "f"(v));
}

// ---------------------------------------------------------------------------
__global__ void zero_kernel() {
    int i = blockIdx.x * blockDim.x + threadIdx.x;
    if (i < HTOT) g_hist[i] = 0.0f;
    if (i == 0) g_done = 0u;
}

// ---------------------------------------------------------------------------
__global__ __launch_bounds__(256, 4)
void hist_kernel(const float* __restrict__ x, const float* __restrict__ y,
                 float* __restrict__ out)
{
    extern __shared__ char P[];
    const unsigned sb = (unsigned)__cvta_generic_to_shared(P);

    const int bx     = blockIdx.x;
    const int split  = bx % SPLITS;
    const int r1     = bx / SPLITS;
    const int c      = r1 % 3;
    const int r2     = r1 / 3;
    const int b      = r2 & 7;
    const int tensor = r2 >> 3;
    const float* img = (tensor ? y : x) + (size_t)b * 3u * PLANE;

    const int base = split * PX_PER_SPLIT;
    const int pend = min(base + PX_PER_SPLIT, PLANE);

    const int t    = threadIdx.x;
    const int lcol = t & 63;                   // bin column in fill phase
    const int sel  = t >> 6;                   // 0..3
    const float cs = fmaf((float)lcol, 300.0f/63.0f, -150.0f); // 50*center

    // GEMM mapping: 2 k-subgroups of 128 threads, 4x8 tile per thread
    const int g     = t >> 7;                  // k-subgroup: 0,1
    const int s     = t & 127;
    const int i0    = (s >> 3) * 4;            // C row base (0..60)
    const int j0    = (s & 7) * 8;             // C col base (0..56)
    const int kbase = g * 32;

    unsigned long long acc[4][4];              // 4 rows x 4 f32x2 col-pairs
    #pragma unroll
    for (int i = 0; i < 4; i++)
        #pragma unroll
        for (int j = 0; j < 4; j++) acc[i][j] = 0ull;

    float* rawp = (float*)(P + OFF_RAW);
    float* up   = (float*)(P + OFF_U);
    float* vp   = (float*)(P + OFF_V);
    float* wp_  = (float*)(P + OFF_W);

    // prefetch chunk 0 raw (threads sel<3: one channel value each)
    float pref = 1.0f;
    {
        int p = base + lcol;
        if (sel < 3 && p < pend) pref = img[sel * PLANE + p];
    }

    for (int chk = 0; chk < NCHUNKS; ++chk) {
        // deposit prefetched raw values
        if (sel < 3) rawp[sel * CHUNK + lcol] = pref;
        __syncthreads();

        // per-pixel params (64 threads)
        if (t < CHUNK) {
            int p = base + chk * CHUNK + t;
            bool valid = p < pend;
            float rr = rawp[t]            + EPS_F;
            float gg = rawp[CHUNK + t]    + EPS_F;
            float bb = rawp[2*CHUNK + t]  + EPS_F;
            float lr = logf(rr), lg = logf(gg), lb = logf(bb);
            float a = lr - lg, d2 = lr - lb;
            float uu, vv;
            if (c == 0)      { uu =  a;  vv = d2;     }
            else if (c == 1) { uu = -a;  vv = d2 - a; }
            else             { uu = -d2; vv = a - d2; }
            up[t]  = uu * 50.0f;
            vp[t]  = vv * 50.0f;
            wp_[t] = valid ? sqrtf(fmaf(rr, rr, fmaf(gg, gg, bb*bb))) : 0.0f;
        }
        // prefetch next chunk
        if (chk + 1 < NCHUNKS) {
            int p = base + (chk + 1) * CHUNK + lcol;
            pref = (sel < 3 && p < pend) ? img[sel * PLANE + p] : 1.0f;
        }
        __syncthreads();

        // fill A2 (dup pairs, w-weighted rbf_u) and B (rbf_v): lane = column
        {
            const int k0 = (sel & 1) * 32;
            if (sel < 2) {
                unsigned aw = sb + OFF_A2 + (unsigned)k0*512u + (unsigned)lcol*8u;
                #pragma unroll 8
                for (int k = 0; k < 32; k++) {
                    float tt = up[k0 + k] - cs;
                    sts_dup(aw, __fdividef(wp_[k0 + k], fmaf(tt, tt, 1.0f)));
                    aw += 512u;
                }
            } else {
                float* Bp = (float*)(P + OFF_B) + k0 * D_HIST + lcol;
                #pragma unroll 8
                for (int k = 0; k < 32; k++) {
                    float tt = vp[k0 + k] - cs;
                    Bp[k * D_HIST] = __fdividef(1.0f, fmaf(tt, tt, 1.0f));
                }
            }
        }
        __syncthreads();

        // GEMM: 32 k-steps, 4 LDS.128 + 16 FFMA2 each (zero MOVs)
        unsigned aA = sb + OFF_A2 + (unsigned)kbase*512u + (unsigned)i0*8u;
        unsigned aB = sb + OFF_B  + (unsigned)kbase*256u + (unsigned)j0*4u;
        #pragma unroll 8
        for (int kk = 0; kk < 32; kk++) {
            unsigned long long p0,p1,p2,p3, q0,q1,q2,q3;
            lds_pair(p0, p1, aA);       lds_pair(p2, p3, aA + 16u);
            lds_pair(q0, q1, aB);       lds_pair(q2, q3, aB + 16u);
            fma2(acc[0][0],p0,q0); fma2(acc[0][1],p0,q1); fma2(acc[0][2],p0,q2); fma2(acc[0][3],p0,q3);
            fma2(acc[1][0],p1,q0); fma2(acc[1][1],p1,q1); fma2(acc[1][2],p1,q2); fma2(acc[1][3],p1,q3);
            fma2(acc[2][0],p2,q0); fma2(acc[2][1],p2,q1); fma2(acc[2][2],p2,q2); fma2(acc[2][3],p2,q3);
            fma2(acc[3][0],p3,q0); fma2(acc[3][1],p3,q1); fma2(acc[3][2],p3,q2); fma2(acc[3][3],p3,q3);
            aA += 512u; aB += 256u;
        }
        // WAR on A2/B is ordered by the first sync of the next iteration
    }

    // ---- combine the 2 k-subgroup partials in shared, then RED.global ----
    __syncthreads();
    float* Csh = (float*)P;                    // reuse A2 region (16 KB)
    for (int i = t; i < D_HIST * D_HIST; i += 256) Csh[i] = 0.0f;
    __syncthreads();
    #pragma unroll
    for (int ii = 0; ii < 4; ii++) {
        #pragma unroll
        for (int jj = 0; jj < 4; jj++) {
            unsigned long long v2 = acc[ii][jj];
            float lo = __uint_as_float((unsigned)(v2 & 0xffffffffull));
            float hi = __uint_as_float((unsigned)(v2 >> 32));
            atomicAdd(&Csh[(i0 + ii) * D_HIST + j0 + 2*jj    ], lo);
            atomicAdd(&Csh[(i0 + ii) * D_HIST + j0 + 2*jj + 1], hi);
        }
    }
    __syncthreads();
    float* dst = g_hist + (size_t)(((tensor * 8) + b) * 3 + c) * (D_HIST*D_HIST);
    for (int i = t; i < D_HIST * D_HIST; i += 256) atomicAdd(&dst[i], Csh[i]);

    // ---- fused finalize: last block reduces ------------------------------
    __threadfence();
    __shared__ unsigned s_last;
    if (t == 0) s_last = (atomicAdd(&g_done, 1u) == (unsigned)(HIST_BLOCKS - 1));
    __syncthreads();
    if (!s_last) return;

    __shared__ float s_red[8];
    __shared__ float s_inv[16];
    __shared__ float s_loss;
    const int lane = t & 31, wp = t >> 5;
    const int PER_B = 3 * D_HIST * D_HIST;     // 12288
    if (t == 0) s_loss = 0.0f;

    for (int gg2 = 0; gg2 < 16; gg2++) {       // totals
        const float* h = g_hist + (size_t)gg2 * PER_B;
        float ssum = 0.0f;
        for (int i = t; i < PER_B; i += 256) ssum += h[i];
        #pragma unroll
        for (int o = 16; o > 0; o >>= 1) ssum += __shfl_down_sync(0xffffffffu, ssum, o);
        if (lane == 0) s_red[wp] = ssum;
        __syncthreads();
        if (t == 0) {
            float v = 0.0f;
            #pragma unroll
            for (int j2 = 0; j2 < 8; j2++) v += s_red[j2];
            s_inv[gg2] = 1.0f / v;
        }
        __syncthreads();
    }

    for (int bb2 = 0; bb2 < 8; bb2++) {
        const float* hx = g_hist + (size_t)bb2 * PER_B;
        const float* hy = g_hist + (size_t)(8 + bb2) * PER_B;
        float ix = s_inv[bb2], iy = s_inv[8 + bb2];
        float a2 = 0.0f;
        for (int i = t; i < PER_B; i += 256) {
            float d = sqrtf(hy[i] * iy) - sqrtf(hx[i] * ix);
            a2 = fmaf(d, d, a2);
        }
        #pragma unroll
        for (int o = 16; o > 0; o >>= 1) a2 += __shfl_down_sync(0xffffffffu, a2, o);
        if (lane == 0) s_red[wp] = a2;
        __syncthreads();
        if (t == 0) {
            float v = 0.0f;
            #pragma unroll
            for (int j2 = 0; j2 < 8; j2++) v += s_red[j2];
            s_loss += sqrtf(v * 0.5f);
        }
        __syncthreads();
    }
    if (t == 0) out[0] = s_loss * 0.125f;
}

// ---------------------------------------------------------------------------
extern "C" void kernel_launch(void* const* d_in, const int* in_sizes, int n_in,
                              void* d_out, int out_size) {
    (void)in_sizes; (void)n_in; (void)out_size;
    const float* x = (const float*)d_in[0];
    const float* y = (const float*)d_in[1];

    cudaFuncSetAttribute((const void*)hist_kernel,
                         cudaFuncAttributeMaxDynamicSharedMemorySize, DYN_SMEM);

    zero_kernel<<<(HTOT + 1023) / 1024, 1024>>>();
    hist_kernel<<<HIST_BLOCKS, 256, DYN_SMEM>>>(x, y, (float*)d_out);
}

// round 11
// speedup vs baseline: 1.3242x; 1.3242x over previous
#include <cuda_runtime.h>
#include <cstdint>
#include <cstddef>

// ---------------------------------------------------------------------------
// ColorHistogramMatchingLoss — balanced FFMA2 GEMM (R10).
//   hist[b,c][i][j] = sum_n w_n * rbf_u(n)[i] * rbf_v(n)[j]
// 8x8 thread tiles, NO smem duplication (1.0 lane-B per lane-FMA: LDS floor ==
// FMA floor == 358us), B operands as direct packed ld.shared.v2.u64, A splat
// in registers, CHUNK=128 single-buffer, 288 blocks (single wave @ 2/SM),
// fused finalize.
// ---------------------------------------------------------------------------

#define D_HIST 64
#define CHUNK  128
#define SPLITS 6
#define PX_PER_SPLIT 10923           // ceil(65536/6)
#define NCHUNKS 86                   // ceil(10923/128)
#define HIST_BLOCKS (2*8*3*SPLITS)   // 288
#define EPS_F  1e-6f
#define PLANE  65536
#define HTOT   (2*8*3*D_HIST*D_HIST)

// dynamic smem layout (bytes from base)
#define OFF_A   0u                   // 128 k-rows x 64 f32 = 32768
#define OFF_B   32768u               // 128 k-rows x 64 f32 = 32768
#define OFF_RAW 65536u               // 3 x 128 f32 = 1536
#define OFF_U   67072u               // 128 f32 (u*50)
#define OFF_V   67584u
#define OFF_W   68096u
#define DYN_SMEM 68608

__device__ float    g_hist[HTOT];
__device__ unsigned g_done;

// ---- packed f32x2 helpers -------------------------------------------------
static __device__ __forceinline__ unsigned long long pk2(float v) {
    unsigned long long r;
    asm("mov.b64 %0, {%1, %1};" : "=l"(r) : "f"(v));
    return r;
}
static __device__ __forceinline__ void fma2(unsigned long long &d,
                                            unsigned long long a,
                                            unsigned long long b) {
    asm("fma.rn.f32x2 %0, %1, %2, %0;" : "+l"(d) : "l"(a), "l"(b));
}
static __device__ __forceinline__ void lds_pair(unsigned long long &a,
                                                unsigned long long &b,
                                                unsigned addr) {
    asm volatile("ld.shared.v2.u64 {%0, %1}, [%2];"
                 : "=l"(a), "=l"(b) : "r"(addr));
}

// ---------------------------------------------------------------------------
__global__ void zero_kernel() {
    int i = blockIdx.x * blockDim.x + threadIdx.x;
    if (i < HTOT) g_hist[i] = 0.0f;
    if (i == 0) g_done = 0u;
}

// ---------------------------------------------------------------------------
__global__ __launch_bounds__(256, 2)
void hist_kernel(const float* __restrict__ x, const float* __restrict__ y,
                 float* __restrict__ out)
{
    extern __shared__ char P[];
    const unsigned sb = (unsigned)__cvta_generic_to_shared(P);

    const int bx     = blockIdx.x;
    const int split  = bx % SPLITS;
    const int r1     = bx / SPLITS;
    const int c      = r1 % 3;
    const int r2     = r1 / 3;
    const int b      = r2 & 7;
    const int tensor = r2 >> 3;
    const float* img = (tensor ? y : x) + (size_t)b * 3u * PLANE;

    const int base = split * PX_PER_SPLIT;
    const int pend = min(base + PX_PER_SPLIT, PLANE);

    const int   t    = threadIdx.x;
    const int   lcol = t & 63;                 // bin column in fill phase
    const int   sel  = t >> 6;                 // 0..3
    const float cs   = fmaf((float)lcol, 300.0f/63.0f, -150.0f); // 50*center

    // GEMM mapping: 4 k-subgroups of 64 threads; 8x8 tile per thread
    const int s     = t & 63;
    const int i0    = (s >> 3) * 8;            // C row base
    const int j0    = (s & 7) * 8;             // C col base
    const int kbase = sel * 32;                // k-slice within chunk

    unsigned long long acc[8][4];              // 8 rows x 4 f32x2 col-pairs
    #pragma unroll
    for (int i = 0; i < 8; i++)
        #pragma unroll
        for (int j = 0; j < 4; j++) acc[i][j] = 0ull;

    float* rawp = (float*)(P + OFF_RAW);
    float* up   = (float*)(P + OFF_U);
    float* vp   = (float*)(P + OFF_V);
    float* wp_  = (float*)(P + OFF_W);

    // raw prefetch mapping: pref0 covers (ch = t>>7, px = t&127),
    //                       pref1 (t<128) covers (ch = 2, px = t)
    const int ch0 = t >> 7, px0 = t & 127;
    auto fetch = [&](int chk, float &f0, float &f1) {
        int p = base + chk * CHUNK;
        int q0 = p + px0;
        f0 = (q0 < pend) ? img[ch0 * PLANE + q0] : 1.0f;
        if (t < 128) {
            int q1 = p + t;
            f1 = (q1 < pend) ? img[2 * PLANE + q1] : 1.0f;
        }
    };

    float pref0 = 1.0f, pref1 = 1.0f;
    fetch(0, pref0, pref1);
    rawp[ch0 * CHUNK + px0] = pref0;
    if (t < 128) rawp[2 * CHUNK + t] = pref1;
    __syncthreads();

    for (int chk = 0; chk < NCHUNKS; ++chk) {
        // ---- prepass: 128 threads, one pixel each (reads raw) ----
        if (t < 128) {
            int p = base + chk * CHUNK + t;
            bool valid = p < pend;
            float rr = rawp[t]            + EPS_F;
            float gg = rawp[CHUNK + t]    + EPS_F;
            float bb = rawp[2*CHUNK + t]  + EPS_F;
            float lr = logf(rr), lg = logf(gg), lb = logf(bb);
            float a = lr - lg, d2 = lr - lb;
            float uu, vv;
            if (c == 0)      { uu =  a;  vv = d2;     }
            else if (c == 1) { uu = -a;  vv = d2 - a; }
            else             { uu = -d2; vv = a - d2; }
            up[t]  = uu * 50.0f;
            vp[t]  = vv * 50.0f;
            wp_[t] = valid ? sqrtf(fmaf(rr, rr, fmaf(gg, gg, bb*bb))) : 0.0f;
        }
        // issue next chunk's global loads (consumed ~2000 cyc later)
        if (chk + 1 < NCHUNKS) fetch(chk + 1, pref0, pref1);
        __syncthreads();

        // ---- fill A[k][i], B[k][j] (plain f32, no duplication) ----
        // sel0: A k 0..63  sel1: A k 64..127  sel2: B k 0..63  sel3: B k 64..127
        {
            const int k0 = (sel & 1) * 64;
            if (sel < 2) {
                float* Ap = (float*)(P + OFF_A) + k0 * D_HIST + lcol;
                #pragma unroll 8
                for (int k = 0; k < 64; k++) {
                    float tt = up[k0 + k] - cs;
                    Ap[k * D_HIST] = __fdividef(wp_[k0 + k], fmaf(tt, tt, 1.0f));
                }
            } else {
                float* Bp = (float*)(P + OFF_B) + k0 * D_HIST + lcol;
                #pragma unroll 8
                for (int k = 0; k < 64; k++) {
                    float tt = vp[k0 + k] - cs;
                    Bp[k * D_HIST] = __fdividef(1.0f, fmaf(tt, tt, 1.0f));
                }
            }
        }
        __syncthreads();

        // ---- GEMM: 32 k-steps; per step 4 LDS.128 + 8 splats + 32 FFMA2 ----
        {
            unsigned aA = sb + OFF_A + (unsigned)kbase*256u + (unsigned)i0*4u;
            unsigned aB = sb + OFF_B + (unsigned)kbase*256u + (unsigned)j0*4u;
            #pragma unroll 8
            for (int kk = 0; kk < 32; kk++) {
                float4 a0 = *(const float4*)(P + (aA - sb));
                float4 a1 = *(const float4*)(P + (aA - sb) + 16u);
                unsigned long long b0, b1, b2, b3;
                lds_pair(b0, b1, aB);
                lds_pair(b2, b3, aB + 16u);
                unsigned long long pa;
                pa = pk2(a0.x); fma2(acc[0][0],pa,b0); fma2(acc[0][1],pa,b1); fma2(acc[0][2],pa,b2); fma2(acc[0][3],pa,b3);
                pa = pk2(a0.y); fma2(acc[1][0],pa,b0); fma2(acc[1][1],pa,b1); fma2(acc[1][2],pa,b2); fma2(acc[1][3],pa,b3);
                pa = pk2(a0.z); fma2(acc[2][0],pa,b0); fma2(acc[2][1],pa,b1); fma2(acc[2][2],pa,b2); fma2(acc[2][3],pa,b3);
                pa = pk2(a0.w); fma2(acc[3][0],pa,b0); fma2(acc[3][1],pa,b1); fma2(acc[3][2],pa,b2); fma2(acc[3][3],pa,b3);
                pa = pk2(a1.x); fma2(acc[4][0],pa,b0); fma2(acc[4][1],pa,b1); fma2(acc[4][2],pa,b2); fma2(acc[4][3],pa,b3);
                pa = pk2(a1.y); fma2(acc[5][0],pa,b0); fma2(acc[5][1],pa,b1); fma2(acc[5][2],pa,b2); fma2(acc[5][3],pa,b3);
                pa = pk2(a1.z); fma2(acc[6][0],pa,b0); fma2(acc[6][1],pa,b1); fma2(acc[6][2],pa,b2); fma2(acc[6][3],pa,b3);
                pa = pk2(a1.w); fma2(acc[7][0],pa,b0); fma2(acc[7][1],pa,b1); fma2(acc[7][2],pa,b2); fma2(acc[7][3],pa,b3);
                aA += 256u; aB += 256u;
            }
        }

        // deposit raw for next chunk (raw last read at prepass, 2 syncs ago)
        if (chk + 1 < NCHUNKS) {
            rawp[ch0 * CHUNK + px0] = pref0;
            if (t < 128) rawp[2 * CHUNK + t] = pref1;
        }
        __syncthreads();   // GEMM done (A/B free) + raw ready
    }

    // ---- combine 4 k-subgroup partials in shared, then RED.global --------
    float* Csh = (float*)P;                    // reuse A region (16 KB)
    for (int i = t; i < D_HIST * D_HIST; i += 256) Csh[i] = 0.0f;
    __syncthreads();
    #pragma unroll
    for (int ii = 0; ii < 8; ii++) {
        #pragma unroll
        for (int jj = 0; jj < 4; jj++) {
            unsigned long long v2 = acc[ii][jj];
            float lo = __uint_as_float((unsigned)(v2 & 0xffffffffull));
            float hi = __uint_as_float((unsigned)(v2 >> 32));
            atomicAdd(&Csh[(i0 + ii) * D_HIST + j0 + 2*jj    ], lo);
            atomicAdd(&Csh[(i0 + ii) * D_HIST + j0 + 2*jj + 1], hi);
        }
    }
    __syncthreads();
    float* dst = g_hist + (size_t)(((tensor * 8) + b) * 3 + c) * (D_HIST*D_HIST);
    for (int i = t; i < D_HIST * D_HIST; i += 256) atomicAdd(&dst[i], Csh[i]);

    // ---- fused finalize: last block reduces ------------------------------
    __threadfence();
    __shared__ unsigned s_last;
    if (t == 0) s_last = (atomicAdd(&g_done, 1u) == (unsigned)(HIST_BLOCKS - 1));
    __syncthreads();
    if (!s_last) return;

    __shared__ float s_red[8];
    __shared__ float s_inv[16];
    __shared__ float s_loss;
    const int lane = t & 31, wp = t >> 5;
    const int PER_B = 3 * D_HIST * D_HIST;     // 12288
    if (t == 0) s_loss = 0.0f;

    for (int gg2 = 0; gg2 < 16; gg2++) {       // per-hist totals
        const float* h = g_hist + (size_t)gg2 * PER_B;
        float ssum = 0.0f;
        for (int i = t; i < PER_B; i += 256) ssum += h[i];
        #pragma unroll
        for (int o = 16; o > 0; o >>= 1) ssum += __shfl_down_sync(0xffffffffu, ssum, o);
        if (lane == 0) s_red[wp] = ssum;
        __syncthreads();
        if (t == 0) {
            float v = 0.0f;
            #pragma unroll
            for (int j2 = 0; j2 < 8; j2++) v += s_red[j2];
            s_inv[gg2] = 1.0f / v;
        }
        __syncthreads();
    }

    for (int bb2 = 0; bb2 < 8; bb2++) {
        const float* hx = g_hist + (size_t)bb2 * PER_B;
        const float* hy = g_hist + (size_t)(8 + bb2) * PER_B;
        float ix = s_inv[bb2], iy = s_inv[8 + bb2];
        float a2 = 0.0f;
        for (int i = t; i < PER_B; i += 256) {
            float d = sqrtf(hy[i] * iy) - sqrtf(hx[i] * ix);
            a2 = fmaf(d, d, a2);
        }
        #pragma unroll
        for (int o = 16; o > 0; o >>= 1) a2 += __shfl_down_sync(0xffffffffu, a2, o);
        if (lane == 0) s_red[wp] = a2;
        __syncthreads();
        if (t == 0) {
            float v = 0.0f;
            #pragma unroll
            for (int j2 = 0; j2 < 8; j2++) v += s_red[j2];
            s_loss += sqrtf(v * 0.5f);
        }
        __syncthreads();
    }
    if (t == 0) out[0] = s_loss * 0.125f;
}

// ---------------------------------------------------------------------------
extern "C" void kernel_launch(void* const* d_in, const int* in_sizes, int n_in,
                              void* d_out, int out_size) {
    (void)in_sizes; (void)n_in; (void)out_size;
    const float* x = (const float*)d_in[0];
    const float* y = (const float*)d_in[1];

    cudaFuncSetAttribute((const void*)hist_kernel,
                         cudaFuncAttributeMaxDynamicSharedMemorySize, DYN_SMEM);

    zero_kernel<<<(HTOT + 1023) / 1024, 1024>>>();
    hist_kernel<<<HIST_BLOCKS, 256, DYN_SMEM>>>(x, y, (float*)d_out);
}